// round 1
// baseline (speedup 1.0000x reference)
#include <cuda_runtime.h>
#include <math.h>

// Problem constants
#define BTOT 131072
#define DIN  768
#define DHID 256
#define DOUT 64
#define NCAT 320            // DHID + DOUT (fused [W1;Wr])
#define NBLK 2048           // BTOT / 64 row-blocks

// ---------------- scratch (device globals; no runtime alloc) ----------------
__device__ float g_X[(size_t)BTOT * DOUT];                 // h_orth, 33.5 MB
__device__ float g_psum[NBLK * DOUT];                      // per-block column sums
__device__ float g_pcov[(size_t)NBLK * DOUT * DOUT];       // per-block X^T X partials
__device__ float g_pcov2[32 * DOUT * DOUT];                // stage-2 reduction
__device__ float g_Cv[DOUT * DOUT];                        // (Wv @ W)/sqrt(sn)
__device__ float g_Cm[DOUT * DOUT];                        // (Wm @ W)/sqrt(sn)
__device__ float g_bv2[DOUT];                              // bv - mu @ Cv^T
__device__ float g_bm2[DOUT];                              // bm - mu @ Cm^T

// smem float counts
#define SMEM1_FLOATS (64 * 257 + 2 * 64 * 65)   // hs + rs + hl (stage1 zs/ws fits inside)
#define SMEM2_FLOATS (4 * 64 * 65)
#define SMEM3_FLOATS (64 * 65 + 2 * 64 * 65)

// =====================================================================
// Kernel 1: per 64-row block:
//   g = z @ [W1;Wr]^T  (one pass over z, N=320)
//   h = GELU(LN(g[:, :256] + b1))
//   hl = h @ W2^T + b2 + (g[:, 256:] + br)
//   X  = hl @ Wo^T   -> g_X, plus partial col-sums and X^T X
// =====================================================================
__global__ void k1_main(const float* __restrict__ z,  const float* __restrict__ W1,
                        const float* __restrict__ b1, const float* __restrict__ lng,
                        const float* __restrict__ lnb, const float* __restrict__ W2,
                        const float* __restrict__ b2, const float* __restrict__ Wr,
                        const float* __restrict__ br, const float* __restrict__ Wo)
{
    extern __shared__ float sm[];
    float* zs = sm;                 // [64][33]  (stage 1 only)
    float* ws = sm + 64 * 33;       // [320][33] (stage 1 only)
    float* hs = sm;                 // [64][257]
    float* rs = sm + 64 * 257;      // [64][65]
    float* hl = rs + 64 * 65;       // [64][65]
    float* os = sm;                 // [64][65], aliases hs (dead by then)

    const int tid = threadIdx.x;
    const int tx = tid & 15, ty = tid >> 4;
    const int m0 = blockIdx.x * 64;

    float acc[4][20];
    #pragma unroll
    for (int i = 0; i < 4; i++)
        #pragma unroll
        for (int j = 0; j < 20; j++) acc[i][j] = 0.f;

    // ---- big GEMM: 64 x 320 x 768, K-chunks of 32 ----
    for (int kk = 0; kk < DIN; kk += 32) {
        #pragma unroll
        for (int t = 0; t < 8; t++) {           // z tile 64x32
            int i = tid + t * 256;
            int row = i >> 5, c = i & 31;
            zs[row * 33 + c] = z[(size_t)(m0 + row) * DIN + kk + c];
        }
        #pragma unroll
        for (int t = 0; t < 40; t++) {          // W tile 320x32
            int i = tid + t * 256;
            int row = i >> 5, c = i & 31;
            const float* srcp = (row < 256) ? (W1 + (size_t)row * DIN)
                                            : (Wr + (size_t)(row - 256) * DIN);
            ws[row * 33 + c] = srcp[kk + c];
        }
        __syncthreads();
        #pragma unroll 8
        for (int k = 0; k < 32; k++) {
            float a[4], bb[20];
            #pragma unroll
            for (int i = 0; i < 4; i++) a[i] = zs[(ty * 4 + i) * 33 + k];
            #pragma unroll
            for (int j = 0; j < 20; j++) bb[j] = ws[(tx + 16 * j) * 33 + k];
            #pragma unroll
            for (int i = 0; i < 4; i++)
                #pragma unroll
                for (int j = 0; j < 20; j++) acc[i][j] += a[i] * bb[j];
        }
        __syncthreads();
    }

    // ---- scatter accumulators + biases into hs / rs ----
    #pragma unroll
    for (int i = 0; i < 4; i++) {
        int row = ty * 4 + i;
        #pragma unroll
        for (int j = 0; j < 20; j++) {
            int col = tx + 16 * j;              // 0..319
            if (col < 256) hs[row * 257 + col] = acc[i][j] + b1[col];
            else           rs[row * 65 + (col - 256)] = acc[i][j] + br[col - 256];
        }
    }
    __syncthreads();

    // ---- LayerNorm + exact GELU, one warp per row ----
    {
        int lane = tid & 31, w = tid >> 5;
        for (int r = w; r < 64; r += 8) {
            float v[8]; float s = 0.f, s2 = 0.f;
            #pragma unroll
            for (int jj = 0; jj < 8; jj++) {
                float x = hs[r * 257 + lane + 32 * jj];
                v[jj] = x; s += x; s2 += x * x;
            }
            #pragma unroll
            for (int o = 16; o > 0; o >>= 1) {
                s  += __shfl_xor_sync(0xffffffffu, s,  o);
                s2 += __shfl_xor_sync(0xffffffffu, s2, o);
            }
            float mean = s * (1.f / 256.f);
            float var  = s2 * (1.f / 256.f) - mean * mean;
            float rstd = rsqrtf(var + 1e-5f);
            #pragma unroll
            for (int jj = 0; jj < 8; jj++) {
                int c = lane + 32 * jj;
                float y = (v[jj] - mean) * rstd * lng[c] + lnb[c];
                hs[r * 257 + c] = 0.5f * y * (1.0f + erff(y * 0.70710678118654752f));
            }
        }
    }
    __syncthreads();

    // ---- hl = hs @ W2^T + b2 + rs   (64x64, K=256) ----
    {
        int j = tid & 63, rg = tid >> 6;
        float a2[16];
        #pragma unroll
        for (int i = 0; i < 16; i++) a2[i] = 0.f;
        #pragma unroll 4
        for (int k = 0; k < 256; k++) {
            float wv = __ldg(&W2[j * 256 + k]);
            #pragma unroll
            for (int i = 0; i < 16; i++) a2[i] += hs[(rg * 16 + i) * 257 + k] * wv;
        }
        #pragma unroll
        for (int i = 0; i < 16; i++) {
            int row = rg * 16 + i;
            hl[row * 65 + j] = a2[i] + b2[j] + rs[row * 65 + j];
        }
    }
    __syncthreads();

    // ---- os = hl @ Wo^T   (64x64, K=64), os aliases hs (dead) ----
    {
        int j = tid & 63, rg = tid >> 6;
        float a2[16];
        #pragma unroll
        for (int i = 0; i < 16; i++) a2[i] = 0.f;
        #pragma unroll 4
        for (int k = 0; k < 64; k++) {
            float wv = __ldg(&Wo[j * 64 + k]);
            #pragma unroll
            for (int i = 0; i < 16; i++) a2[i] += hl[(rg * 16 + i) * 65 + k] * wv;
        }
        #pragma unroll
        for (int i = 0; i < 16; i++) os[(rg * 16 + i) * 65 + j] = a2[i];
    }
    __syncthreads();

    // ---- write X, partial column-sums, partial X^T X ----
    for (int i = tid; i < 4096; i += 256) {
        int row = i >> 6, j = i & 63;
        g_X[(size_t)(m0 + row) * 64 + j] = os[row * 65 + j];
    }
    if (tid < 64) {
        float s = 0.f;
        #pragma unroll 8
        for (int r = 0; r < 64; r++) s += os[r * 65 + tid];
        g_psum[blockIdx.x * 64 + tid] = s;
    }
    {
        int j2 = tid & 63, g = tid >> 6;
        #pragma unroll
        for (int i = 0; i < 16; i++) {
            int j1 = g * 16 + i;
            float s = 0.f;
            #pragma unroll 8
            for (int r = 0; r < 64; r++) s += os[r * 65 + j1] * os[r * 65 + j2];
            g_pcov[(size_t)blockIdx.x * 4096 + j1 * 64 + j2] = s;
        }
    }
}

// =====================================================================
// Kernel R: deterministic tree reduce of g_pcov: 2048 -> 32 partials
// =====================================================================
__global__ void k_red()
{
    int gt = blockIdx.x * 256 + threadIdx.x;   // 0 .. 131071
    int e = gt & 4095, ch = gt >> 12;          // ch in 0..31
    const float* p = g_pcov + (size_t)ch * 64 * 4096 + e;
    float s = 0.f;
    #pragma unroll 8
    for (int b = 0; b < 64; b++) s += p[(size_t)b * 4096];
    g_pcov2[ch * 4096 + e] = s;
}

// =====================================================================
// Kernel 2 (1 block): mu, sigma, Newton-Schulz (5 iters), fold into
// Cv=(Wv@W)/sqrt(sn), Cm=(Wm@W)/sqrt(sn), bv2, bm2.
// =====================================================================
__global__ void k2_ns(const float* __restrict__ Wv, const float* __restrict__ bv,
                      const float* __restrict__ Wm, const float* __restrict__ bm)
{
    extern __shared__ float sm[];
    float* Ss = sm;                 // sigma_scaled [64][65]
    float* Wp = sm + 4160;          // W iterate
    float* T1 = sm + 8320;
    float* T2 = sm + 12480;
    __shared__ float mu[64];
    __shared__ float snorm_s;

    const int tid = threadIdx.x;
    const float Bf = (float)BTOT;

    // mu
    {
        int col = tid & 63, q = tid >> 6;
        float s = 0.f;
        for (int b = q; b < NBLK; b += 4) s += g_psum[b * 64 + col];
        T1[q * 64 + col] = s;
        __syncthreads();
        if (tid < 64)
            mu[tid] = (T1[tid] + T1[64 + tid] + T1[128 + tid] + T1[192 + tid]) / Bf;
        __syncthreads();
    }
    // raw sigma into T2
    for (int i = tid; i < 4096; i += 256) {
        int j1 = i >> 6, j2 = i & 63;
        float c = 0.f;
        #pragma unroll 8
        for (int ch = 0; ch < 32; ch++) c += g_pcov2[ch * 4096 + i];
        float sig = (c - Bf * mu[j1] * mu[j2]) / (Bf - 1.0f);
        if (j1 == j2) sig += 0.001f;
        T2[j1 * 65 + j2] = sig;
    }
    __syncthreads();
    // trace -> sigma_norm
    if (tid < 32) {
        float t = T2[tid * 65 + tid] + T2[(tid + 32) * 65 + (tid + 32)];
        #pragma unroll
        for (int o = 16; o > 0; o >>= 1) t += __shfl_xor_sync(0xffffffffu, t, o);
        if (tid == 0) snorm_s = t * 1.5f + 1e-6f;
    }
    __syncthreads();
    float snorm = snorm_s;
    for (int i = tid; i < 4096; i += 256) {
        int j1 = i >> 6, j2 = i & 63;
        Ss[j1 * 65 + j2] = T2[j1 * 65 + j2] / snorm;
        Wp[j1 * 65 + j2] = (j1 == j2) ? 1.f : 0.f;
    }
    __syncthreads();

    const int j = tid & 63, rg = tid >> 6;
    for (int it = 0; it < 5; it++) {
        // T1 = W @ Ss
        #pragma unroll
        for (int i = 0; i < 16; i++) {
            int r = rg * 16 + i; float s = 0.f;
            #pragma unroll 8
            for (int k = 0; k < 64; k++) s += Wp[r * 65 + k] * Ss[k * 65 + j];
            T1[r * 65 + j] = s;
        }
        __syncthreads();
        // T2 = T1 @ W^T   (= P)
        #pragma unroll
        for (int i = 0; i < 16; i++) {
            int r = rg * 16 + i; float s = 0.f;
            #pragma unroll 8
            for (int k = 0; k < 64; k++) s += T1[r * 65 + k] * Wp[j * 65 + k];
            T2[r * 65 + j] = s;
        }
        __syncthreads();
        // T1 = 1.5 W - 0.5 (P @ W)
        #pragma unroll
        for (int i = 0; i < 16; i++) {
            int r = rg * 16 + i; float s = 0.f;
            #pragma unroll 8
            for (int k = 0; k < 64; k++) s += T2[r * 65 + k] * Wp[k * 65 + j];
            T1[r * 65 + j] = 1.5f * Wp[r * 65 + j] - 0.5f * s;
        }
        __syncthreads();
        for (int i = tid; i < 4160; i += 256) Wp[i] = T1[i];
        __syncthreads();
    }

    float iss = rsqrtf(snorm);
    // Cv = (Wv @ W) * iss  -> T1 & g_Cv
    {
        int kcol = tid & 63, jg = tid >> 6;
        #pragma unroll
        for (int i = 0; i < 16; i++) {
            int jr = jg * 16 + i; float s = 0.f;
            #pragma unroll 8
            for (int d = 0; d < 64; d++) s += __ldg(&Wv[jr * 64 + d]) * Wp[d * 65 + kcol];
            float c = s * iss;
            T1[jr * 65 + kcol] = c;
            g_Cv[jr * 64 + kcol] = c;
        }
    }
    __syncthreads();
    if (tid < 64) {
        float s = 0.f;
        #pragma unroll 8
        for (int k = 0; k < 64; k++) s += mu[k] * T1[tid * 65 + k];
        g_bv2[tid] = bv[tid] - s;
    }
    // Cm = (Wm @ W) * iss -> T2 & g_Cm
    {
        int kcol = tid & 63, jg = tid >> 6;
        #pragma unroll
        for (int i = 0; i < 16; i++) {
            int jr = jg * 16 + i; float s = 0.f;
            #pragma unroll 8
            for (int d = 0; d < 64; d++) s += __ldg(&Wm[jr * 64 + d]) * Wp[d * 65 + kcol];
            float c = s * iss;
            T2[jr * 65 + kcol] = c;
            g_Cm[jr * 64 + kcol] = c;
        }
    }
    __syncthreads();
    if (tid < 64) {
        float s = 0.f;
        #pragma unroll 8
        for (int k = 0; k < 64; k++) s += mu[k] * T2[tid * 65 + k];
        g_bm2[tid] = bm[tid] - s;
    }
}

// =====================================================================
// Kernel 3: out = (X @ Cv^T + bv2) * sigmoid(X @ Cm^T + bm2) * scale
// =====================================================================
__global__ void k3_out(float* __restrict__ out, const float* __restrict__ scale)
{
    extern __shared__ float sm[];
    float* Xs  = sm;            // [64][65]
    float* Cvs = sm + 4160;     // [64][65]
    float* Cms = sm + 8320;     // [64][65]
    const int tid = threadIdx.x;
    const int m0 = blockIdx.x * 64;

    for (int i = tid; i < 4096; i += 256) {
        int row = i >> 6, j = i & 63;
        Xs[row * 65 + j]  = g_X[(size_t)(m0 + row) * 64 + j];
        Cvs[row * 65 + j] = g_Cv[i];
        Cms[row * 65 + j] = g_Cm[i];
    }
    __syncthreads();

    const int j = tid & 63, rg = tid >> 6;
    const float bv2 = g_bv2[j], bm2 = g_bm2[j], sc = scale[0];
    #pragma unroll
    for (int i = 0; i < 16; i++) {
        int row = rg * 16 + i;
        float av = 0.f, am = 0.f;
        #pragma unroll 8
        for (int k = 0; k < 64; k++) {
            float x = Xs[row * 65 + k];
            av += x * Cvs[j * 65 + k];
            am += x * Cms[j * 65 + k];
        }
        float m = 1.f / (1.f + expf(-(am + bm2)));
        out[(size_t)(m0 + row) * 64 + j] = (av + bv2) * m * sc;
    }
}

// =====================================================================
extern "C" void kernel_launch(void* const* d_in, const int* in_sizes, int n_in,
                              void* d_out, int out_size)
{
    (void)in_sizes; (void)n_in; (void)out_size;
    const float* z    = (const float*)d_in[0];
    const float* W1   = (const float*)d_in[1];
    const float* b1   = (const float*)d_in[2];
    const float* ln_g = (const float*)d_in[3];
    const float* ln_b = (const float*)d_in[4];
    const float* W2   = (const float*)d_in[5];
    const float* b2   = (const float*)d_in[6];
    const float* Wr   = (const float*)d_in[7];
    const float* br   = (const float*)d_in[8];
    const float* Wo   = (const float*)d_in[9];
    const float* Wv   = (const float*)d_in[10];
    const float* bv   = (const float*)d_in[11];
    const float* Wm   = (const float*)d_in[12];
    const float* bm   = (const float*)d_in[13];
    const float* scale = (const float*)d_in[14];
    float* out = (float*)d_out;

    const int smem1 = SMEM1_FLOATS * 4;
    const int smem2 = SMEM2_FLOATS * 4;
    const int smem3 = SMEM3_FLOATS * 4;
    cudaFuncSetAttribute(k1_main, cudaFuncAttributeMaxDynamicSharedMemorySize, smem1);
    cudaFuncSetAttribute(k2_ns,   cudaFuncAttributeMaxDynamicSharedMemorySize, smem2);
    cudaFuncSetAttribute(k3_out,  cudaFuncAttributeMaxDynamicSharedMemorySize, smem3);

    k1_main<<<NBLK, 256, smem1>>>(z, W1, b1, ln_g, ln_b, W2, b2, Wr, br, Wo);
    k_red<<<512, 256>>>();
    k2_ns<<<1, 256, smem2>>>(Wv, bv, Wm, bm);
    k3_out<<<NBLK, 256, smem3>>>(out, scale);
}